// round 15
// baseline (speedup 1.0000x reference)
#include <cuda_runtime.h>
#include <cstdint>

#define NN 100000
#define EE 1600000
#define NB_SCAN 391   // ceil(NN/256)

// copy slice boundaries (float4 units); total = EE*16 = 25,600,000
#define C_EP0 0
#define C_EP1 6000000
#define C_G0  C_EP1
#define C_G0E 8200000
#define C_A0  C_G0E
#define C_A0E 12700000
#define C_G1  C_A0E
#define C_G1E 14900000
#define C_A1  C_G1E
#define C_A1E 19400000
#define C_G2  C_A1E
#define C_G2E 21600000
#define C_A2  C_G2E
#define C_A2E 25600000

// ---------------- scratch (static device globals; no allocation) ----------------
__device__ int    g_cnt[NN];
__device__ int    g_off[NN + 1];
__device__ int    g_cursor[NN];
__device__ int    g_bsum[512];
__device__ float4 g_csr[EE];       // {src_as_float, t0, t1, t2} grouped by dst
__device__ float  g_h[NN * 64];    // h = x' @ W
__device__ float  g_s[NN];         // x' . (W a_s)
__device__ float  g_d[NN];         // x' . (W a_d)
__device__ float  g_x1[NN * 64];   // layer output ping
__device__ float  g_x2[NN * 64];   // layer output pong
__device__ float  g_we[3][64];     // We @ a_e
__device__ float  g_ws[3][64];     // W  @ a_s
__device__ float  g_wd[3][64];     // W  @ a_d

// ---------------- grid-stride copy helper (4x unrolled for MLP) ----------------
__device__ __forceinline__ void copy_slice(const float4* __restrict__ src,
                                           float4* __restrict__ dst,
                                           int beg, int end, int gl, int stride) {
    int i = beg + gl;
    for (; i + 3 * stride < end; i += 4 * stride) {
        float4 a = src[i];
        float4 b = src[i + stride];
        float4 c = src[i + 2 * stride];
        float4 d = src[i + 3 * stride];
        dst[i]              = a;
        dst[i + stride]     = b;
        dst[i + 2 * stride] = c;
        dst[i + 3 * stride] = d;
    }
    for (; i < end; i += stride) dst[i] = src[i];
}

// ---------------- per-layer projected attention vectors ----------------
__global__ void k_prep(const float* __restrict__ We, const float* __restrict__ W,
                       const float* __restrict__ a_e, const float* __restrict__ a_s,
                       const float* __restrict__ a_d) {
    int l = blockIdx.x, k = threadIdx.x;
    const float* wer = We + l * 4096 + k * 64;
    const float* wr  = W  + l * 4096 + k * 64;
    float se = 0.f, ss = 0.f, sd = 0.f;
#pragma unroll
    for (int j = 0; j < 64; j++) {
        se += wer[j] * a_e[l * 64 + j];
        ss += wr[j]  * a_s[l * 64 + j];
        sd += wr[j]  * a_d[l * 64 + j];
    }
    g_we[l][k] = se; g_ws[l][k] = ss; g_wd[l][k] = sd;
}

// ---------------- in-degree histogram ----------------
__global__ void k_hist(const int* __restrict__ ei) {
    int e = blockIdx.x * 256 + threadIdx.x;
    if (e < EE) atomicAdd(&g_cnt[ei[EE + e]], 1);
}

// ---------------- exclusive prefix scan of g_cnt -> g_off (3 kernels) ----------------
__global__ void k_scan_block() {
    int t = threadIdx.x, i = blockIdx.x * 256 + t;
    int v = (i < NN) ? g_cnt[i] : 0;
    int lane = t & 31, w = t >> 5;
    int incl = v;
#pragma unroll
    for (int o = 1; o < 32; o <<= 1) {
        int n = __shfl_up_sync(0xffffffffu, incl, o);
        if (lane >= o) incl += n;
    }
    __shared__ int wt[8];
    if (lane == 31) wt[w] = incl;
    __syncthreads();
    if (t < 8) {
        int x = wt[t], ix = x;
#pragma unroll
        for (int o = 1; o < 8; o <<= 1) {
            int n = __shfl_up_sync(0xffu, ix, o);
            if (t >= o) ix += n;
        }
        wt[t] = ix - x;   // exclusive warp base
    }
    __syncthreads();
    int excl = incl - v + wt[w];
    if (i < NN) g_off[i] = excl;
    if (t == 255) g_bsum[blockIdx.x] = excl + v;
}

__global__ void k_scan_top(int nb) {
    __shared__ int sm[512];
    int t = threadIdx.x;
    sm[t] = (t < nb) ? g_bsum[t] : 0;
    __syncthreads();
    for (int o = 1; o < 512; o <<= 1) {
        int v = (t >= o) ? sm[t - o] : 0;
        __syncthreads();
        sm[t] += v;
        __syncthreads();
    }
    int ex = (t == 0) ? 0 : sm[t - 1];
    if (t < nb) g_bsum[t] = ex;
}

__global__ void k_scan_add() {
    int i = blockIdx.x * 256 + threadIdx.x;
    if (i < NN) {
        int o = g_off[i] + g_bsum[blockIdx.x];
        g_off[i] = o;
        g_cursor[i] = o;
    }
    if (i == 0) g_off[NN] = EE;
}

// ---------------- edge scan + copy warp: 8 edge-warps + 1 copy warp per block ----------------
__global__ __launch_bounds__(288) void k_edge_pre(const float* __restrict__ eattr,
                                                  const int* __restrict__ ei,
                                                  const float4* __restrict__ csrc,
                                                  float4* __restrict__ cdst) {
    __shared__ float we_s[3][64];
    int tid = threadIdx.x;
    if (tid < 192) ((float*)we_s)[tid] = ((const float*)g_we)[tid];
    __syncthreads();
    if (tid >= 256) {
        // dedicated copy warp
        int gl = blockIdx.x * 32 + (tid - 256);
        copy_slice(csrc, cdst, C_EP0, C_EP1, gl, gridDim.x * 32);
        return;
    }
    int lane = tid & 31;
    int e = blockIdx.x * 8 + (tid >> 5);
    if (e >= EE) return;
    float2 v = ((const float2*)(eattr + (size_t)e * 64))[lane];
    float t0 = v.x * we_s[0][2 * lane] + v.y * we_s[0][2 * lane + 1];
    float t1 = v.x * we_s[1][2 * lane] + v.y * we_s[1][2 * lane + 1];
    float t2 = v.x * we_s[2][2 * lane] + v.y * we_s[2][2 * lane + 1];
#pragma unroll
    for (int o = 16; o > 0; o >>= 1) {
        t0 += __shfl_down_sync(0xffffffffu, t0, o);
        t1 += __shfl_down_sync(0xffffffffu, t1, o);
        t2 += __shfl_down_sync(0xffffffffu, t2, o);
    }
    if (lane == 0) {
        int dst = ei[EE + e];
        int pos = atomicAdd(&g_cursor[dst], 1);
        g_csr[pos] = make_float4(__int_as_float(ei[e]), t0, t1, t2);
    }
}

// ---------------- gemm + 2 copy warps: threads 0-255 compute, 256-319 copy ----------------
__global__ __launch_bounds__(320) void k_gemm(const float* __restrict__ x,
                                              const float* __restrict__ W,
                                              const float* __restrict__ wsv,
                                              const float* __restrict__ wdv,
                                              int dorelu,
                                              const float4* __restrict__ csrc,
                                              float4* __restrict__ cdst,
                                              int cbeg, int cend) {
    __shared__ float Ws[64 * 64];
    __shared__ float xs[128][68];
    __shared__ float wss[64], wds[64];
    int tid = threadIdx.x;
    int base = blockIdx.x * 128;
    int rows = min(128, NN - base);
    if (tid < 256) {
#pragma unroll
        for (int i = 0; i < 16; i++) Ws[tid + i * 256] = W[tid + i * 256];
        if (tid < 64) { wss[tid] = wsv[tid]; wds[tid] = wdv[tid]; }
        for (int i = tid; i < rows * 16; i += 256) {
            int r = i >> 4, c4 = i & 15;
            float4 v = ((const float4*)(x + (size_t)(base + r) * 64))[c4];
            if (dorelu) {
                v.x = fmaxf(v.x, 0.f); v.y = fmaxf(v.y, 0.f);
                v.z = fmaxf(v.z, 0.f); v.w = fmaxf(v.w, 0.f);
            }
            float* p = &xs[r][c4 * 4];
            p[0] = v.x; p[1] = v.y; p[2] = v.z; p[3] = v.w;
        }
    }
    __syncthreads();

    if (tid >= 256) {
        // dedicated copy warps overlap with the FFMA-bound compute below
        int gl = blockIdx.x * 64 + (tid - 256);
        copy_slice(csrc, cdst, cbeg, cend, gl, gridDim.x * 64);
        return;
    }

    int rg = tid >> 4;          // rows rg*8 .. rg*8+7
    int cg = (tid & 15) * 4;    // cols cg .. cg+3
    float acc[8][4];
#pragma unroll
    for (int j = 0; j < 8; j++) {
        acc[j][0] = 0.f; acc[j][1] = 0.f; acc[j][2] = 0.f; acc[j][3] = 0.f;
    }
#pragma unroll 8
    for (int k = 0; k < 64; k++) {
        float4 w = *(const float4*)(Ws + k * 64 + cg);
#pragma unroll
        for (int j = 0; j < 8; j++) {
            float xv = xs[rg * 8 + j][k];
            acc[j][0] += xv * w.x;
            acc[j][1] += xv * w.y;
            acc[j][2] += xv * w.z;
            acc[j][3] += xv * w.w;
        }
    }
#pragma unroll
    for (int j = 0; j < 8; j++) {
        int r = rg * 8 + j;
        if (r < rows)
            *(float4*)(g_h + (size_t)(base + r) * 64 + cg) =
                make_float4(acc[j][0], acc[j][1], acc[j][2], acc[j][3]);
    }
    if (tid < 128 && tid < rows) {
        float sv = 0.f, dv = 0.f;
#pragma unroll 16
        for (int k = 0; k < 64; k++) {
            float xv = xs[tid][k];
            sv += xv * wss[k];
            dv += xv * wds[k];
        }
        g_s[base + tid] = sv;
        g_d[base + tid] = dv;
    }
}

// ---------------- CSR aggregation + 1 copy warp per block ----------------
template <int L>
__global__ __launch_bounds__(288) void k_agg(float* __restrict__ dest,
                                             const float* __restrict__ bias,
                                             const float4* __restrict__ csrc,
                                             float4* __restrict__ cdst,
                                             int cbeg, int cend) {
    int tid = threadIdx.x;
    if (tid >= 256) {
        int gl = blockIdx.x * 32 + (tid - 256);
        copy_slice(csrc, cdst, cbeg, cend, gl, gridDim.x * 32);
        return;
    }
    int node = blockIdx.x * 16 + (tid >> 4);
    if (node >= NN) return;
    int hl = tid & 15;
    int hb = tid & 16;                      // half-warp base within warp
    unsigned mask = 0xFFFFu << hb;

    int beg = g_off[node], end = g_off[node + 1];
    float dn = g_d[node];
    float4 acc = make_float4(0.f, 0.f, 0.f, 0.f);
    float denomp = 0.f, tsump = 0.f;

    for (int chunk = beg; chunk < end; chunk += 16) {
        int e = chunk + hl;
        int srcv = 0; float ea = 0.f, tv = 0.f;
        if (e < end) {
            float4 c = g_csr[e];
            srcv = __float_as_int(c.x);
            tv = (L == 0) ? c.y : ((L == 1) ? c.z : c.w);
            float a = g_s[srcv] + dn + tv;
            a = (a >= 0.f) ? a : 0.2f * a;
            ea = __expf(a);
        }
        denomp += ea;
        tsump  += tv;
        int lim = min(16, end - chunk);
        if (lim == 16) {
#pragma unroll
            for (int j = 0; j < 16; j++) {
                int   sj = __shfl_sync(mask, srcv, hb + j);
                float ej = __shfl_sync(mask, ea,   hb + j);
                float4 hv = *(const float4*)(g_h + (size_t)sj * 64 + hl * 4);
                acc.x += ej * hv.x; acc.y += ej * hv.y;
                acc.z += ej * hv.z; acc.w += ej * hv.w;
            }
        } else {
            for (int j = 0; j < lim; j++) {
                int   sj = __shfl_sync(mask, srcv, hb + j);
                float ej = __shfl_sync(mask, ea,   hb + j);
                float4 hv = *(const float4*)(g_h + (size_t)sj * 64 + hl * 4);
                acc.x += ej * hv.x; acc.y += ej * hv.y;
                acc.z += ej * hv.z; acc.w += ej * hv.w;
            }
        }
    }
#pragma unroll
    for (int o = 8; o > 0; o >>= 1) {
        denomp += __shfl_xor_sync(mask, denomp, o);
        tsump  += __shfl_xor_sync(mask, tsump,  o);
    }
    int deg = end - beg;
    float tself = tsump / fmaxf((float)deg, 1.f);
    float a = g_s[node] + dn + tself;
    a = (a >= 0.f) ? a : 0.2f * a;
    float eas = __expf(a);
    float4 hv = *(const float4*)(g_h + (size_t)node * 64 + hl * 4);
    acc.x += eas * hv.x; acc.y += eas * hv.y;
    acc.z += eas * hv.z; acc.w += eas * hv.w;
    float inv = 1.f / (denomp + eas);
    float4 b = ((const float4*)bias)[hl];
    ((float4*)(dest + (size_t)node * 64))[hl] =
        make_float4(acc.x * inv + b.x, acc.y * inv + b.y,
                    acc.z * inv + b.z, acc.w * inv + b.w);
}

extern "C" void kernel_launch(void* const* d_in, const int* in_sizes, int n_in,
                              void* d_out, int out_size) {
    const float* node  = (const float*)d_in[0];
    const float* ehid  = (const float*)d_in[1];
    const float* eattr = (const float*)d_in[2];
    const int*   ei    = (const int*)d_in[3];
    const float* W     = (const float*)d_in[4];
    const float* We    = (const float*)d_in[5];
    const float* a_s   = (const float*)d_in[6];
    const float* a_d   = (const float*)d_in[7];
    const float* a_e   = (const float*)d_in[8];
    const float* bias  = (const float*)d_in[9];
    float* out = (float*)d_out;

    const float4* csrc = (const float4*)ehid;
    float4* cdst = (float4*)(out + (size_t)NN * 64);

    void *p_cnt, *p_x1, *p_x2, *p_ws, *p_wd;
    cudaGetSymbolAddress(&p_cnt, g_cnt);
    cudaGetSymbolAddress(&p_x1,  g_x1);
    cudaGetSymbolAddress(&p_x2,  g_x2);
    cudaGetSymbolAddress(&p_ws,  g_ws);
    cudaGetSymbolAddress(&p_wd,  g_wd);

    cudaMemsetAsync(p_cnt, 0, sizeof(int) * NN, 0);
    k_hist<<<(EE + 255) / 256, 256>>>(ei);
    k_scan_block<<<NB_SCAN, 256>>>();
    k_scan_top<<<1, 512>>>(NB_SCAN);
    k_scan_add<<<NB_SCAN, 256>>>();
    k_prep<<<3, 64>>>(We, W, a_e, a_s, a_d);
    k_edge_pre<<<EE / 8, 288>>>(eattr, ei, csrc, cdst);

    const float* wsv = (const float*)p_ws;
    const float* wdv = (const float*)p_wd;
    float* x1 = (float*)p_x1;
    float* x2 = (float*)p_x2;
    const int GB = (NN + 127) / 128;   // gemm grid
    const int AB = (NN + 15) / 16;     // agg grid

    // layer 0
    k_gemm<<<GB, 320>>>(node, W + 0 * 4096, wsv + 0, wdv + 0, 0,
                        csrc, cdst, C_G0, C_G0E);
    k_agg<0><<<AB, 288>>>(x1, bias + 0 * 64, csrc, cdst, C_A0, C_A0E);
    // layer 1
    k_gemm<<<GB, 320>>>(x1, W + 1 * 4096, wsv + 64, wdv + 64, 1,
                        csrc, cdst, C_G1, C_G1E);
    k_agg<1><<<AB, 288>>>(x2, bias + 1 * 64, csrc, cdst, C_A1, C_A1E);
    // layer 2
    k_gemm<<<GB, 320>>>(x2, W + 2 * 4096, wsv + 128, wdv + 128, 1,
                        csrc, cdst, C_G2, C_G2E);
    k_agg<2><<<AB, 288>>>(out, bias + 2 * 64, csrc, cdst, C_A2, C_A2E);
}

// round 17
// speedup vs baseline: 1.0941x; 1.0941x over previous
#include <cuda_runtime.h>
#include <cstdint>

#define NN 100000
#define EE 1600000
#define NB_SCAN 391   // ceil(NN/256)

// copy slices (float4 units), total = EE*16 = 25,600,000
#define C_EP_BEG 0
#define C_EP_END 10000000
#define C_A0_BEG 10000000
#define C_A0_END 15200000
#define C_A1_BEG 15200000
#define C_A1_END 20400000
#define C_A2_BEG 20400000
#define C_A2_END 25600000

#define EP_GRID 203175   // 3175 copy blocks (every 64th) + 200000 compute
#define AG_GRID 7143     // 893 copy blocks (every 8th)   + 6250 compute
#define EP_CSTRIDE (3175 * 256)
#define AG_CSTRIDE (893 * 256)

// ---------------- scratch (static device globals; no allocation) ----------------
__device__ int    g_cnt[NN];
__device__ int    g_off[NN + 1];
__device__ int    g_cursor[NN];
__device__ int    g_bsum[512];
__device__ float4 g_csr[EE];       // {src_as_float, t0, t1, t2} grouped by dst
__device__ float  g_h[NN * 64];    // h = x' @ W
__device__ float  g_s[NN];         // x' . (W a_s)
__device__ float  g_d[NN];         // x' . (W a_d)
__device__ float  g_x1[NN * 64];   // layer output ping
__device__ float  g_x2[NN * 64];   // layer output pong
__device__ float  g_we[3][64];     // We @ a_e
__device__ float  g_ws[3][64];     // W  @ a_s
__device__ float  g_wd[3][64];     // W  @ a_d

// ---------------- strided copy helper (4x unrolled for MLP) ----------------
__device__ __forceinline__ void copy_slice(const float4* __restrict__ src,
                                           float4* __restrict__ dst,
                                           int beg, int end, int gl, int stride) {
    int i = beg + gl;
    for (; i + 3 * stride < end; i += 4 * stride) {
        float4 a = src[i];
        float4 b = src[i + stride];
        float4 c = src[i + 2 * stride];
        float4 d = src[i + 3 * stride];
        dst[i]              = a;
        dst[i + stride]     = b;
        dst[i + 2 * stride] = c;
        dst[i + 3 * stride] = d;
    }
    for (; i < end; i += stride) dst[i] = src[i];
}

// ---------------- per-layer projected attention vectors ----------------
__global__ void k_prep(const float* __restrict__ We, const float* __restrict__ W,
                       const float* __restrict__ a_e, const float* __restrict__ a_s,
                       const float* __restrict__ a_d) {
    int l = blockIdx.x, k = threadIdx.x;
    const float* wer = We + l * 4096 + k * 64;
    const float* wr  = W  + l * 4096 + k * 64;
    float se = 0.f, ss = 0.f, sd = 0.f;
#pragma unroll
    for (int j = 0; j < 64; j++) {
        se += wer[j] * a_e[l * 64 + j];
        ss += wr[j]  * a_s[l * 64 + j];
        sd += wr[j]  * a_d[l * 64 + j];
    }
    g_we[l][k] = se; g_ws[l][k] = ss; g_wd[l][k] = sd;
}

// ---------------- in-degree histogram ----------------
__global__ void k_hist(const int* __restrict__ ei) {
    int e = blockIdx.x * 256 + threadIdx.x;
    if (e < EE) atomicAdd(&g_cnt[ei[EE + e]], 1);
}

// ---------------- exclusive prefix scan of g_cnt -> g_off (3 kernels) ----------------
__global__ void k_scan_block() {
    int t = threadIdx.x, i = blockIdx.x * 256 + t;
    int v = (i < NN) ? g_cnt[i] : 0;
    int lane = t & 31, w = t >> 5;
    int incl = v;
#pragma unroll
    for (int o = 1; o < 32; o <<= 1) {
        int n = __shfl_up_sync(0xffffffffu, incl, o);
        if (lane >= o) incl += n;
    }
    __shared__ int wt[8];
    if (lane == 31) wt[w] = incl;
    __syncthreads();
    if (t < 8) {
        int x = wt[t], ix = x;
#pragma unroll
        for (int o = 1; o < 8; o <<= 1) {
            int n = __shfl_up_sync(0xffu, ix, o);
            if (t >= o) ix += n;
        }
        wt[t] = ix - x;   // exclusive warp base
    }
    __syncthreads();
    int excl = incl - v + wt[w];
    if (i < NN) g_off[i] = excl;
    if (t == 255) g_bsum[blockIdx.x] = excl + v;
}

__global__ void k_scan_top(int nb) {
    __shared__ int sm[512];
    int t = threadIdx.x;
    sm[t] = (t < nb) ? g_bsum[t] : 0;
    __syncthreads();
    for (int o = 1; o < 512; o <<= 1) {
        int v = (t >= o) ? sm[t - o] : 0;
        __syncthreads();
        sm[t] += v;
        __syncthreads();
    }
    int ex = (t == 0) ? 0 : sm[t - 1];
    if (t < nb) g_bsum[t] = ex;
}

__global__ void k_scan_add() {
    int i = blockIdx.x * 256 + threadIdx.x;
    if (i < NN) {
        int o = g_off[i] + g_bsum[blockIdx.x];
        g_off[i] = o;
        g_cursor[i] = o;
    }
    if (i == 0) g_off[NN] = EE;
}

// ---------------- edge scan with interleaved copy blocks (every 64th block) ----------------
__global__ __launch_bounds__(256) void k_edge_pre(const float* __restrict__ eattr,
                                                  const int* __restrict__ ei,
                                                  const float4* __restrict__ csrc,
                                                  float4* __restrict__ cdst) {
    int tid = threadIdx.x;
    int b = blockIdx.x;
    if ((b & 63) == 0) {
        int gl = (b >> 6) * 256 + tid;
        copy_slice(csrc, cdst, C_EP_BEG, C_EP_END, gl, EP_CSTRIDE);
        return;
    }
    int cb = b - (b >> 6) - 1;   // compute-block index 0..199999
    __shared__ float we_s[3][64];
    if (tid < 192) ((float*)we_s)[tid] = ((const float*)g_we)[tid];
    __syncthreads();
    int lane = tid & 31;
    int e = cb * 8 + (tid >> 5);
    if (e >= EE) return;
    float2 v = ((const float2*)(eattr + (size_t)e * 64))[lane];
    float t0 = v.x * we_s[0][2 * lane] + v.y * we_s[0][2 * lane + 1];
    float t1 = v.x * we_s[1][2 * lane] + v.y * we_s[1][2 * lane + 1];
    float t2 = v.x * we_s[2][2 * lane] + v.y * we_s[2][2 * lane + 1];
#pragma unroll
    for (int o = 16; o > 0; o >>= 1) {
        t0 += __shfl_down_sync(0xffffffffu, t0, o);
        t1 += __shfl_down_sync(0xffffffffu, t1, o);
        t2 += __shfl_down_sync(0xffffffffu, t2, o);
    }
    if (lane == 0) {
        int dst = ei[EE + e];
        int pos = atomicAdd(&g_cursor[dst], 1);
        g_csr[pos] = make_float4(__int_as_float(ei[e]), t0, t1, t2);
    }
}

// ---------------- h = x' @ W ; s = x'.ws ; d = x'.wd ;  x' = dorelu ? relu(x) : x ----------------
__global__ __launch_bounds__(256) void k_gemm(const float* __restrict__ x,
                                              const float* __restrict__ W,
                                              const float* __restrict__ wsv,
                                              const float* __restrict__ wdv,
                                              int dorelu) {
    __shared__ float Ws[64 * 64];
    __shared__ float xs[128][68];
    __shared__ float wss[64], wds[64];
    int tid = threadIdx.x;
#pragma unroll
    for (int i = 0; i < 16; i++) Ws[tid + i * 256] = W[tid + i * 256];
    if (tid < 64) { wss[tid] = wsv[tid]; wds[tid] = wdv[tid]; }

    int base = blockIdx.x * 128;
    int rows = min(128, NN - base);
    for (int i = tid; i < rows * 16; i += 256) {
        int r = i >> 4, c4 = i & 15;
        float4 v = ((const float4*)(x + (size_t)(base + r) * 64))[c4];
        if (dorelu) {
            v.x = fmaxf(v.x, 0.f); v.y = fmaxf(v.y, 0.f);
            v.z = fmaxf(v.z, 0.f); v.w = fmaxf(v.w, 0.f);
        }
        float* p = &xs[r][c4 * 4];
        p[0] = v.x; p[1] = v.y; p[2] = v.z; p[3] = v.w;
    }
    __syncthreads();

    int rg = tid >> 4;          // rows rg*8 .. rg*8+7
    int cg = (tid & 15) * 4;    // cols cg .. cg+3
    float acc[8][4];
#pragma unroll
    for (int j = 0; j < 8; j++) {
        acc[j][0] = 0.f; acc[j][1] = 0.f; acc[j][2] = 0.f; acc[j][3] = 0.f;
    }
#pragma unroll 8
    for (int k = 0; k < 64; k++) {
        float4 w = *(const float4*)(Ws + k * 64 + cg);
#pragma unroll
        for (int j = 0; j < 8; j++) {
            float xv = xs[rg * 8 + j][k];
            acc[j][0] += xv * w.x;
            acc[j][1] += xv * w.y;
            acc[j][2] += xv * w.z;
            acc[j][3] += xv * w.w;
        }
    }
#pragma unroll
    for (int j = 0; j < 8; j++) {
        int r = rg * 8 + j;
        if (r < rows)
            *(float4*)(g_h + (size_t)(base + r) * 64 + cg) =
                make_float4(acc[j][0], acc[j][1], acc[j][2], acc[j][3]);
    }
    if (tid < 128 && tid < rows) {
        float sv = 0.f, dv = 0.f;
#pragma unroll 16
        for (int k = 0; k < 64; k++) {
            float xv = xs[tid][k];
            sv += xv * wss[k];
            dv += xv * wds[k];
        }
        g_s[base + tid] = sv;
        g_d[base + tid] = dv;
    }
}

// ---------------- CSR aggregation with interleaved copy blocks (every 8th block) ----------------
template <int L>
__global__ __launch_bounds__(256) void k_agg(float* __restrict__ dest,
                                             const float* __restrict__ bias,
                                             const float4* __restrict__ csrc,
                                             float4* __restrict__ cdst,
                                             int cbeg, int cend) {
    int tid = threadIdx.x;
    int b = blockIdx.x;
    if ((b & 7) == 0) {
        int gl = (b >> 3) * 256 + tid;
        copy_slice(csrc, cdst, cbeg, cend, gl, AG_CSTRIDE);
        return;
    }
    int cb = b - (b >> 3) - 1;   // compute-block index 0..6249
    int node = cb * 16 + (tid >> 4);
    if (node >= NN) return;
    int hl = tid & 15;
    int hb = tid & 16;                      // half-warp base within warp
    unsigned mask = 0xFFFFu << hb;

    int beg = g_off[node], end = g_off[node + 1];
    float dn = g_d[node];
    float4 acc = make_float4(0.f, 0.f, 0.f, 0.f);
    float denomp = 0.f, tsump = 0.f;

    for (int chunk = beg; chunk < end; chunk += 16) {
        int e = chunk + hl;
        int srcv = 0; float ea = 0.f, tv = 0.f;
        if (e < end) {
            float4 c = g_csr[e];
            srcv = __float_as_int(c.x);
            tv = (L == 0) ? c.y : ((L == 1) ? c.z : c.w);
            float a = g_s[srcv] + dn + tv;
            a = (a >= 0.f) ? a : 0.2f * a;
            ea = __expf(a);
        }
        denomp += ea;
        tsump  += tv;
        int lim = min(16, end - chunk);
        if (lim == 16) {
#pragma unroll
            for (int j = 0; j < 16; j++) {
                int   sj = __shfl_sync(mask, srcv, hb + j);
                float ej = __shfl_sync(mask, ea,   hb + j);
                float4 hv = *(const float4*)(g_h + (size_t)sj * 64 + hl * 4);
                acc.x += ej * hv.x; acc.y += ej * hv.y;
                acc.z += ej * hv.z; acc.w += ej * hv.w;
            }
        } else {
            for (int j = 0; j < lim; j++) {
                int   sj = __shfl_sync(mask, srcv, hb + j);
                float ej = __shfl_sync(mask, ea,   hb + j);
                float4 hv = *(const float4*)(g_h + (size_t)sj * 64 + hl * 4);
                acc.x += ej * hv.x; acc.y += ej * hv.y;
                acc.z += ej * hv.z; acc.w += ej * hv.w;
            }
        }
    }
#pragma unroll
    for (int o = 8; o > 0; o >>= 1) {
        denomp += __shfl_xor_sync(mask, denomp, o);
        tsump  += __shfl_xor_sync(mask, tsump,  o);
    }
    int deg = end - beg;
    float tself = tsump / fmaxf((float)deg, 1.f);
    float a = g_s[node] + dn + tself;
    a = (a >= 0.f) ? a : 0.2f * a;
    float eas = __expf(a);
    float4 hv = *(const float4*)(g_h + (size_t)node * 64 + hl * 4);
    acc.x += eas * hv.x; acc.y += eas * hv.y;
    acc.z += eas * hv.z; acc.w += eas * hv.w;
    float inv = 1.f / (denomp + eas);
    float4 b4 = ((const float4*)bias)[hl];
    ((float4*)(dest + (size_t)node * 64))[hl] =
        make_float4(acc.x * inv + b4.x, acc.y * inv + b4.y,
                    acc.z * inv + b4.z, acc.w * inv + b4.w);
}

extern "C" void kernel_launch(void* const* d_in, const int* in_sizes, int n_in,
                              void* d_out, int out_size) {
    const float* node  = (const float*)d_in[0];
    const float* ehid  = (const float*)d_in[1];
    const float* eattr = (const float*)d_in[2];
    const int*   ei    = (const int*)d_in[3];
    const float* W     = (const float*)d_in[4];
    const float* We    = (const float*)d_in[5];
    const float* a_s   = (const float*)d_in[6];
    const float* a_d   = (const float*)d_in[7];
    const float* a_e   = (const float*)d_in[8];
    const float* bias  = (const float*)d_in[9];
    float* out = (float*)d_out;

    const float4* csrc = (const float4*)ehid;
    float4* cdst = (float4*)(out + (size_t)NN * 64);

    void *p_cnt, *p_x1, *p_x2, *p_ws, *p_wd;
    cudaGetSymbolAddress(&p_cnt, g_cnt);
    cudaGetSymbolAddress(&p_x1,  g_x1);
    cudaGetSymbolAddress(&p_x2,  g_x2);
    cudaGetSymbolAddress(&p_ws,  g_ws);
    cudaGetSymbolAddress(&p_wd,  g_wd);

    cudaMemsetAsync(p_cnt, 0, sizeof(int) * NN, 0);
    k_hist<<<(EE + 255) / 256, 256>>>(ei);
    k_scan_block<<<NB_SCAN, 256>>>();
    k_scan_top<<<1, 512>>>(NB_SCAN);
    k_scan_add<<<NB_SCAN, 256>>>();
    k_prep<<<3, 64>>>(We, W, a_e, a_s, a_d);
    k_edge_pre<<<EP_GRID, 256>>>(eattr, ei, csrc, cdst);

    const float* wsv = (const float*)p_ws;
    const float* wdv = (const float*)p_wd;
    float* x1 = (float*)p_x1;
    float* x2 = (float*)p_x2;
    const int GB = (NN + 127) / 128;

    // layer 0
    k_gemm<<<GB, 256>>>(node, W + 0 * 4096, wsv + 0, wdv + 0, 0);
    k_agg<0><<<AG_GRID, 256>>>(x1, bias + 0 * 64, csrc, cdst, C_A0_BEG, C_A0_END);
    // layer 1
    k_gemm<<<GB, 256>>>(x1, W + 1 * 4096, wsv + 64, wdv + 64, 1);
    k_agg<1><<<AG_GRID, 256>>>(x2, bias + 1 * 64, csrc, cdst, C_A1_BEG, C_A1_END);
    // layer 2
    k_gemm<<<GB, 256>>>(x2, W + 2 * 4096, wsv + 128, wdv + 128, 1);
    k_agg<2><<<AG_GRID, 256>>>(out, bias + 2 * 64, csrc, cdst, C_A2_BEG, C_A2_END);
}